// round 3
// baseline (speedup 1.0000x reference)
#include <cuda_runtime.h>
#include <cuda_bf16.h>

// Problem constants
#define NN   131072     // nodes per branch
#define GG   4096       // graphs
#define NPGC 32         // nodes per graph
#define EE   1048576    // edges per branch
#define SS   64         // state size
#define HH   128        // hidden size
#define NCH  (EE / 32)  // 32768 warp-chunks per branch
#define MAXREL 65536    // compacted-edge capacity per branch (expect ~32768)
#define GPB  16         // graphs per block in finish

// ---------------- device scratch (zero-initialized at module load) --------
__device__ unsigned g_pack[2][MAXREL];   // (graph<<17) | src
__device__ int      g_cnt[2];            // compacted counts (reset by k_finish)
__device__ float    g_adst[2][GG];       // a_dst at self node per graph
__device__ float    g_num[2][GG][SS];    // sum_e p_e * x[src_e] (zeroed by k_finish)
__device__ float    g_den[2][GG];        // sum_e p_e          (zeroed by k_finish)

// ---------------- helpers ----------------
__device__ __forceinline__ int detect_is64(const void* eidx) {
    // int64 edge buffer: odd 32-bit words are high halves == 0.
    // int32 buffer: odd words are src[1,3,...] — all-zero has ~0 probability.
    const unsigned* raw = (const unsigned*)eidx;
    int f = 1;
#pragma unroll
    for (int i = 0; i < 16; i++) f &= (raw[2 * i + 1] == 0u);
    return f;
}

// ============ kernel A: scan+compact edges, compute a_dst ============
// grid: dim3(528, 2). blockIdx.y = branch.
//   blocks 0..15  : a_dst  (4096 threads = 1 graph/thread)
//   blocks 16..527: dst scan + ballot compaction (4096 warps, 2-chunk unroll)
__global__ void k_scan(const void* __restrict__ up_e, const void* __restrict__ dn_e,
                       const float* __restrict__ upx, const float* __restrict__ dnx,
                       const float* __restrict__ upW, const float* __restrict__ up_ad,
                       const float* __restrict__ dnW, const float* __restrict__ dn_ad) {
    const int branch = blockIdx.y;
    const void*  eidx = branch ? dn_e : up_e;
    const float* x    = branch ? dnx  : upx;
    const int t = threadIdx.x;

    if (blockIdx.x < 16) {
        // ---- a_dst blocks ----
        const float* W  = branch ? dnW  : upW;
        const float* ad = branch ? dn_ad : up_ad;
        __shared__ float wd[SS];           // w_dst = W @ att_dst
        if (t < SS) {
            float acc = 0.0f;
#pragma unroll 8
            for (int h = 0; h < HH; h++) acc += W[t * HH + h] * ad[h];
            wd[t] = acc;
        }
        __syncthreads();
        int g = blockIdx.x * 256 + t;      // 0..4095
        const float4* xr = (const float4*)(x + (size_t)(g * NPGC + NPGC - 1) * SS);
        const float4* wv = (const float4*)wd;
        float acc = 0.0f;
#pragma unroll
        for (int i = 0; i < 16; i++) {
            float4 v = xr[i];
            float4 w = wv[i];
            acc += v.x * w.x + v.y * w.y + v.z * w.z + v.w * w.w;
        }
        g_adst[branch][g] = acc;
        return;
    }

    // ---- scan blocks ----
    const int is64 = detect_is64(eidx);
    const int lane = t & 31;
    const int wid  = t >> 5;
    const int gw   = (blockIdx.x - 16) * 8 + wid;      // 0..4095
    const int nw   = (gridDim.x - 16) * 8;             // 4096
    const int*       e32 = (const int*)eidx;
    const long long* e64 = (const long long*)eidx;

    for (int c = gw * 2; c < NCH; c += nw * 2) {
        int i0 = c * 32 + lane;
        int i1 = i0 + 32;
        int d0 = is64 ? (int)e64[EE + i0] : e32[EE + i0];
        int d1 = is64 ? (int)e64[EE + i1] : e32[EE + i1];

        // chunk 0
        {
            bool rel = ((d0 & 31) == 31);
            unsigned m = __ballot_sync(0xffffffffu, rel);
            if (m) {
                int n = __popc(m);
                int base = 0;
                if (lane == 0) base = atomicAdd(&g_cnt[branch], n);
                base = __shfl_sync(0xffffffffu, base, 0);
                if (rel) {
                    int rank = __popc(m & ((1u << lane) - 1));
                    int pos = base + rank;
                    if (pos < MAXREL) {
                        int src = is64 ? (int)e64[i0] : e32[i0];
                        g_pack[branch][pos] = ((unsigned)(d0 >> 5) << 17) | (unsigned)src;
                    }
                }
            }
        }
        // chunk 1
        {
            bool rel = ((d1 & 31) == 31);
            unsigned m = __ballot_sync(0xffffffffu, rel);
            if (m) {
                int n = __popc(m);
                int base = 0;
                if (lane == 0) base = atomicAdd(&g_cnt[branch], n);
                base = __shfl_sync(0xffffffffu, base, 0);
                if (rel) {
                    int rank = __popc(m & ((1u << lane) - 1));
                    int pos = base + rank;
                    if (pos < MAXREL) {
                        int src = is64 ? (int)e64[i1] : e32[i1];
                        g_pack[branch][pos] = ((unsigned)(d1 >> 5) << 17) | (unsigned)src;
                    }
                }
            }
        }
    }
}

// ============ kernel B: process compacted edges ============
// grid: dim3(128, 2). One warp handles groups of 4 consecutive edges (MLP 4).
__global__ void k_edges(const float* __restrict__ upx, const float* __restrict__ dnx,
                        const float* __restrict__ upW, const float* __restrict__ up_as,
                        const float* __restrict__ dnW, const float* __restrict__ dn_as) {
    const int branch = blockIdx.y;
    const float* x  = branch ? dnx  : upx;
    const float* W  = branch ? dnW  : upW;
    const float* as = branch ? dn_as : up_as;

    __shared__ float ws[SS];               // w_src = W @ att_src
    const int t = threadIdx.x;
    if (t < SS) {
        float acc = 0.0f;
#pragma unroll 8
        for (int h = 0; h < HH; h++) acc += W[t * HH + h] * as[h];
        ws[t] = acc;
    }
    __syncthreads();

    const int lane = t & 31;
    const int gw = blockIdx.x * 8 + (t >> 5);
    const int nw = gridDim.x * 8;
    int cnt = g_cnt[branch];
    if (cnt > MAXREL) cnt = MAXREL;

    const float2 wv = ((const float2*)ws)[lane];
    const unsigned* __restrict__ pk = g_pack[branch];
    const float* __restrict__ adst = g_adst[branch];

    for (int i = gw * 4; i < cnt; i += nw * 4) {
        unsigned p[4];
        float2   xv[4];
        bool     act[4];
#pragma unroll
        for (int k = 0; k < 4; k++) {
            act[k] = (i + k < cnt);
            p[k] = act[k] ? pk[i + k] : 0u;          // uniform (broadcast) load
        }
#pragma unroll
        for (int k = 0; k < 4; k++) {
            int src = (int)(p[k] & 0x1FFFFu);
            xv[k] = act[k] ? ((const float2*)(x + (size_t)src * SS))[lane]
                           : make_float2(0.f, 0.f);   // 4 gathers in flight
        }
#pragma unroll
        for (int k = 0; k < 4; k++) {
            if (!act[k]) continue;
            int g = (int)(p[k] >> 17);
            float part = xv[k].x * wv.x + xv[k].y * wv.y;
#pragma unroll
            for (int o = 16; o; o >>= 1)
                part += __shfl_xor_sync(0xffffffffu, part, o);
            float e = part + adst[g];
            e = (e > 0.0f) ? e : 0.2f * e;            // leaky_relu
            float pr = __expf(e);

            float* num = g_num[branch][g];
            atomicAdd(num + 2 * lane,     pr * xv[k].x);
            atomicAdd(num + 2 * lane + 1, pr * xv[k].y);
            if (lane == 0) atomicAdd(&g_den[branch][g], pr);
        }
    }
}

// ============ kernel C: finish + scratch reset ============
// 256 blocks x 256 threads, 16 graphs/block. Each thread holds one W column
// in registers (reused across 16 graphs). Also zeroes num/den and counters
// for the next graph replay.
__global__ void k_finish(const float* __restrict__ upW, const float* __restrict__ upb,
                         const float* __restrict__ dnW, const float* __restrict__ dnb,
                         const float* __restrict__ mlpW, const float* __restrict__ mlpb,
                         float* __restrict__ out) {
    const int t = threadIdx.x;     // 0..255
    const int b = t >> 7;          // branch
    const int h = t & 127;
    const float* W = b ? dnW : upW;

    float Wcol[SS];
#pragma unroll
    for (int s = 0; s < SS; s++) Wcol[s] = W[s * HH + h];
    const float bias = b ? dnb[h] : upb[h];
    const float mw = mlpW[h];
    const float mb = mlpb[0];

    __shared__ float xs[2][SS];
    __shared__ float dnsig[HH];
    __shared__ float part[4];

    const int g0 = blockIdx.x * GPB;
    for (int i = 0; i < GPB; i++) {
        int g = g0 + i;
        if (t < 128) {
            int bb = t >> 6, s = t & 63;
            float den = g_den[bb][g] + 1e-16f;
            xs[bb][s] = g_num[bb][g][s] / den;
        }
        __syncthreads();
        // zero accumulators for next replay (reads above are complete)
        if (t < 128) g_num[t >> 6][g][t & 63] = 0.0f;
        if (t == 128) g_den[0][g] = 0.0f;
        if (t == 129) g_den[1][g] = 0.0f;

        float acc = bias;
        const float4* xv = (const float4*)xs[b];
#pragma unroll
        for (int s4 = 0; s4 < SS / 4; s4++) {
            float4 v = xv[s4];
            acc += v.x * Wcol[4 * s4]     + v.y * Wcol[4 * s4 + 1]
                 + v.z * Wcol[4 * s4 + 2] + v.w * Wcol[4 * s4 + 3];
        }
        float sig = 1.0f / (1.0f + __expf(-acc));
        if (b) dnsig[h] = sig;
        __syncthreads();
        if (!b) {
            float v = sig * dnsig[h] * mw;
#pragma unroll
            for (int o = 16; o; o >>= 1) v += __shfl_xor_sync(0xffffffffu, v, o);
            if ((t & 31) == 0) part[t >> 5] = v;
        }
        __syncthreads();
        if (t == 0) out[g] = part[0] + part[1] + part[2] + part[3] + mb;
        __syncthreads();   // protect smem reuse next iteration
    }
    if (blockIdx.x == 0 && t == 0) { g_cnt[0] = 0; g_cnt[1] = 0; }
}

// ---------------- launch ----------------
extern "C" void kernel_launch(void* const* d_in, const int* in_sizes, int n_in,
                              void* d_out, int out_size) {
    const float* up_x    = (const float*)d_in[0];
    const void*  up_eidx = d_in[1];
    const float* dn_x    = (const float*)d_in[3];
    const void*  dn_eidx = d_in[4];
    const float* upW     = (const float*)d_in[6];
    const float* up_as   = (const float*)d_in[7];
    const float* up_ad   = (const float*)d_in[8];
    const float* up_b    = (const float*)d_in[9];
    const float* dnW     = (const float*)d_in[10];
    const float* dn_as   = (const float*)d_in[11];
    const float* dn_ad   = (const float*)d_in[12];
    const float* dn_b    = (const float*)d_in[13];
    const float* mlpW    = (const float*)d_in[14];
    const float* mlpb    = (const float*)d_in[15];
    float* out = (float*)d_out;

    k_scan  <<<dim3(528, 2), 256>>>(up_eidx, dn_eidx, up_x, dn_x,
                                    upW, up_ad, dnW, dn_ad);
    k_edges <<<dim3(128, 2), 256>>>(up_x, dn_x, upW, up_as, dnW, dn_as);
    k_finish<<<256, 256>>>(upW, up_b, dnW, dn_b, mlpW, mlpb, out);
}

// round 6
// speedup vs baseline: 2.0832x; 2.0832x over previous
#include <cuda_runtime.h>
#include <cuda_bf16.h>

// Problem constants
#define NN   131072     // nodes per branch
#define GG   4096       // graphs
#define NPGC 32         // nodes per graph
#define EE   1048576    // edges per branch
#define SS   64         // state size
#define HH   128        // hidden size
#define NCH  (EE / 32)  // 32768 warp-chunks of 32 edges per branch
#define CAP  40         // bucket capacity per graph (Poisson(8); P(>40) ~ 1e-16)
#define GPB  16         // graphs per block in fused finish

// -------- device scratch (zero-initialized at load; counters reset in K2) --
__device__ int   g_bcnt[2][GG];          // edges captured per graph
__device__ int   g_bucket[2][GG][CAP];   // src node ids of relevant edges
__device__ float g_adst[2][GG];          // a_dst at self node per graph
__device__ float g_wsrc[2][SS];          // W @ att_src per branch

// ---------------- helpers ----------------
__device__ __forceinline__ int detect_is64(const void* eidx) {
    // int64 buffer: odd 32-bit words (high halves) are 0. With int32 node
    // ids, 16 consecutive odd words all-zero has ~0 probability.
    const unsigned* raw = (const unsigned*)eidx;
    int f = 1;
#pragma unroll
    for (int i = 0; i < 16; i++) f &= (raw[2 * i + 1] == 0u);
    return f;
}

// ============ kernel 1: scan dst -> per-graph buckets; a_dst; w_src ========
// grid dim3(272, 2); blockIdx.y = branch.
//   blocks 0..15  : a_dst (thread per graph) + (block 0) w_src fold
//   blocks 16..271: dst scan, 8-chunk batches per warp (MLP 8)
__global__ void __launch_bounds__(256)
k_scan(const void* __restrict__ up_e, const void* __restrict__ dn_e,
       const float* __restrict__ upx, const float* __restrict__ dnx,
       const float* __restrict__ upW, const float* __restrict__ up_ad,
       const float* __restrict__ up_as,
       const float* __restrict__ dnW, const float* __restrict__ dn_ad,
       const float* __restrict__ dn_as) {
    const int branch = blockIdx.y;
    const void*  eidx = branch ? dn_e : up_e;
    const float* x    = branch ? dnx  : upx;
    const int t = threadIdx.x;

    if (blockIdx.x < 16) {
        const float* W  = branch ? dnW   : upW;
        const float* ad = branch ? dn_ad : up_ad;
        const float* as = branch ? dn_as : up_as;
        __shared__ float wd[SS];
        if (t < SS) {
            float accd = 0.0f;
#pragma unroll 8
            for (int h = 0; h < HH; h++) accd += W[t * HH + h] * ad[h];
            wd[t] = accd;
            if (blockIdx.x == 0) {           // fold w_src once per branch
                float accs = 0.0f;
#pragma unroll 8
                for (int h = 0; h < HH; h++) accs += W[t * HH + h] * as[h];
                g_wsrc[branch][t] = accs;
            }
        }
        __syncthreads();
        int g = blockIdx.x * 256 + t;        // 0..4095
        const float4* xr = (const float4*)(x + (size_t)(g * NPGC + NPGC - 1) * SS);
        const float4* wv = (const float4*)wd;
        float acc = 0.0f;
#pragma unroll
        for (int i = 0; i < 16; i++) {
            float4 v = xr[i], w = wv[i];
            acc += v.x * w.x + v.y * w.y + v.z * w.z + v.w * w.w;
        }
        g_adst[branch][g] = acc;
        return;
    }

    // ---- scan partition: 256 blocks x 8 warps = 2048 warps per branch ----
    const int is64 = detect_is64(eidx);
    const int lane = t & 31;
    const int gw   = (blockIdx.x - 16) * 8 + (t >> 5);   // 0..2047
    const int*       e32 = (const int*)eidx;
    const long long* e64 = (const long long*)eidx;

#pragma unroll
    for (int it = 0; it < 2; it++) {
        const int cbase = it * 16384 + gw * 8;           // 8 chunks per batch
        int d[8];
#pragma unroll
        for (int k = 0; k < 8; k++) {                    // 8 loads in flight
            int idx = (cbase + k) * 32 + lane;
            d[k] = is64 ? (int)e64[EE + idx] : e32[EE + idx];
        }
#pragma unroll
        for (int k = 0; k < 8; k++) {
            if ((d[k] & 31) == 31) {
                int g = d[k] >> 5;
                int pos = atomicAdd(&g_bcnt[branch][g], 1);
                if (pos < CAP) {
                    int idx = (cbase + k) * 32 + lane;
                    int src = is64 ? (int)e64[idx] : e32[idx];
                    g_bucket[branch][g][pos] = src;
                }
            }
        }
    }
}

// ============ kernel 2: per-graph aggregate + projection + output =========
// 256 blocks x 256 threads, 16 graphs/block.
// Phase A: warp per (graph, branch): gather ~8 src rows, softmax-weighted
//          mean of x rows, all in registers, no atomics. Resets counters.
// Phase B: h = xs@W + bias (W column per thread in registers), sigmoid.
// Phase C: out[g] = sum_h sig_up*sig_dn*mlpW[h] + mlpb.
__global__ void __launch_bounds__(256)
k_finish(const float* __restrict__ upx, const float* __restrict__ dnx,
         const float* __restrict__ upW, const float* __restrict__ upb,
         const float* __restrict__ dnW, const float* __restrict__ dnb,
         const float* __restrict__ mlpW, const float* __restrict__ mlpb,
         float* __restrict__ out) {
    const int t    = threadIdx.x;
    const int lane = t & 31;
    const int wid  = t >> 5;
    const int g0   = blockIdx.x * GPB;

    __shared__ float xs[2][GPB][SS];     // weighted-mean x per (branch, graph)
    __shared__ float sg[2][GPB][HH];     // sigmoid(h) per (branch, graph)

    // preload W column for phase B (independent of phase A)
    const int pb = t >> 7, ph = t & 127;
    const float* Wp = pb ? dnW : upW;
    float Wcol[SS];
#pragma unroll
    for (int s = 0; s < SS; s++) Wcol[s] = Wp[s * HH + ph];
    const float bias = pb ? dnb[ph] : upb[ph];

    // ---------- phase A ----------
    {
        const int b = wid & 1;
        const float* x = b ? dnx : upx;
        const float2 wv = ((const float2*)g_wsrc[b])[lane];
#pragma unroll
        for (int sweep = 0; sweep < 4; sweep++) {
            const int gi = sweep * 4 + (wid >> 1);
            const int g  = g0 + gi;
            int cnt = g_bcnt[b][g];
            if (cnt > CAP) cnt = CAP;
            const float adst = g_adst[b][g];
            float2 acc = make_float2(0.f, 0.f);
            float  den = 0.0f;
            const int* __restrict__ bk = g_bucket[b][g];

            for (int e0 = 0; e0 < cnt; e0 += 8) {
                const int ne = cnt - e0 < 8 ? cnt - e0 : 8;
                float2 xv[8];
                float  pd[8];
#pragma unroll
                for (int k = 0; k < 8; k++) {
                    if (k < ne) {
                        int src = bk[e0 + k];            // broadcast load
                        xv[k] = ((const float2*)(x + (size_t)src * SS))[lane];
                    } else xv[k] = make_float2(0.f, 0.f);
                }
#pragma unroll
                for (int k = 0; k < 8; k++)
                    pd[k] = xv[k].x * wv.x + xv[k].y * wv.y;
                // 8 interleaved butterfly reductions (pipelined)
#pragma unroll
                for (int o = 16; o; o >>= 1)
#pragma unroll
                    for (int k = 0; k < 8; k++)
                        pd[k] += __shfl_xor_sync(0xffffffffu, pd[k], o);
#pragma unroll
                for (int k = 0; k < 8; k++) {
                    if (k < ne) {
                        float e = pd[k] + adst;
                        e = (e > 0.0f) ? e : 0.2f * e;   // leaky_relu
                        float p = __expf(e);
                        den += p;
                        acc.x += p * xv[k].x;
                        acc.y += p * xv[k].y;
                    }
                }
            }
            float inv = 1.0f / (den + 1e-16f);
            xs[b][gi][2 * lane]     = acc.x * inv;
            xs[b][gi][2 * lane + 1] = acc.y * inv;
            if (lane == 0) g_bcnt[b][g] = 0;             // reset for replay
        }
    }
    __syncthreads();

    // ---------- phase B ----------
#pragma unroll 4
    for (int i = 0; i < GPB; i++) {
        float acc = bias;
        const float4* xv = (const float4*)xs[pb][i];
#pragma unroll
        for (int s4 = 0; s4 < SS / 4; s4++) {
            float4 v = xv[s4];
            acc += v.x * Wcol[4 * s4]     + v.y * Wcol[4 * s4 + 1]
                 + v.z * Wcol[4 * s4 + 2] + v.w * Wcol[4 * s4 + 3];
        }
        sg[pb][i][ph] = 1.0f / (1.0f + __expf(-acc));
    }
    __syncthreads();

    // ---------- phase C ----------
    const float4 mw4 = ((const float4*)mlpW)[lane];
    const float  mb  = mlpb[0];
#pragma unroll
    for (int sweep = 0; sweep < 2; sweep++) {
        const int i = sweep * 8 + wid;
        const float4 su = ((const float4*)sg[0][i])[lane];
        const float4 sd = ((const float4*)sg[1][i])[lane];
        float v = su.x * sd.x * mw4.x + su.y * sd.y * mw4.y
                + su.z * sd.z * mw4.z + su.w * sd.w * mw4.w;
#pragma unroll
        for (int o = 16; o; o >>= 1) v += __shfl_xor_sync(0xffffffffu, v, o);
        if (lane == 0) out[g0 + i] = v + mb;
    }
}

// ---------------- launch ----------------
extern "C" void kernel_launch(void* const* d_in, const int* in_sizes, int n_in,
                              void* d_out, int out_size) {
    const float* up_x    = (const float*)d_in[0];
    const void*  up_eidx = d_in[1];
    const float* dn_x    = (const float*)d_in[3];
    const void*  dn_eidx = d_in[4];
    const float* upW     = (const float*)d_in[6];
    const float* up_as   = (const float*)d_in[7];
    const float* up_ad   = (const float*)d_in[8];
    const float* up_b    = (const float*)d_in[9];
    const float* dnW     = (const float*)d_in[10];
    const float* dn_as   = (const float*)d_in[11];
    const float* dn_ad   = (const float*)d_in[12];
    const float* dn_b    = (const float*)d_in[13];
    const float* mlpW    = (const float*)d_in[14];
    const float* mlpb    = (const float*)d_in[15];
    float* out = (float*)d_out;

    k_scan  <<<dim3(272, 2), 256>>>(up_eidx, dn_eidx, up_x, dn_x,
                                    upW, up_ad, up_as, dnW, dn_ad, dn_as);
    k_finish<<<256, 256>>>(up_x, dn_x, upW, up_b, dnW, dn_b, mlpW, mlpb, out);
}